// round 2
// baseline (speedup 1.0000x reference)
#include <cuda_runtime.h>
#include <cuda_bf16.h>
#include <math.h>
#include <stdint.h>

// Problem constants
#define BATCH 32
#define SEQ   512
#define IN_D  512
#define HID   1024
#define G3    3072   // 3*HID
#define NCTA  128    // persistent scan grid size (must all be co-resident)

typedef unsigned long long ull;

// packed f32x2 FMA: d = a*b + d (elementwise on two packed fp32)
#define FMA2(acc, a, b) asm("fma.rn.f32x2 %0, %1, %2, %0;" : "+l"(acc) : "l"(a), "l"(b))
#define DUPF(d, x) asm("mov.b64 %0, {%1, %1};" : "=l"(d) : "r"(__float_as_uint(x)))

__device__ __forceinline__ float psum(ull p) {
    unsigned lo, hi;
    asm("mov.b64 {%0, %1}, %2;" : "=r"(lo), "=r"(hi) : "l"(p));
    return __uint_as_float(lo) + __uint_as_float(hi);
}
__device__ __forceinline__ void unpk(ull p, float& a, float& b) {
    unsigned lo, hi;
    asm("mov.b64 {%0, %1}, %2;" : "=r"(lo), "=r"(hi) : "l"(p));
    a = __uint_as_float(lo); b = __uint_as_float(hi);
}

// ---------------------------------------------------------------------------
// Scratch (device globals; zero-initialized at module load)
// ---------------------------------------------------------------------------
__device__ float g_gx[(size_t)SEQ * BATCH * G3];   // reused for both layers
__device__ float g_y0[(size_t)SEQ * BATCH * HID];  // layer0 hidden history
__device__ float g_y1[(size_t)SEQ * BATCH * HID];  // layer1 hidden history
__device__ float g_h0[BATCH * HID];                // zeros, never written

// grid barrier state
__device__ unsigned g_count;   // zero-init
__device__ unsigned g_gen;     // zero-init, monotonic across replays (relative compare)

// ---------------------------------------------------------------------------
// SGEMM (fp32 via FFMA2, NT): C[m][n] = sum_k A[m][k]*W[n][k] + bias[n]
// A row offset = (m>>5)*a_s0 + (m&31)*a_s1 ; C row offset = (m>>5)*c_s0 + (m&31)*c_s1
// BM=BN=128, BK=16, 256 threads, 8x8 per thread (acc packed along n).
// ---------------------------------------------------------------------------
__global__ __launch_bounds__(256)
void sgemm_nt(const float* __restrict__ A, const float* __restrict__ W,
              const float* __restrict__ bias, float* __restrict__ C,
              int K,
              int a_s0, int a_s1, int c_s0, int c_s1)
{
    __shared__ float As[16][132];
    __shared__ float Ws[16][132];

    const int bm = blockIdx.y * 128;
    const int bn = blockIdx.x * 128;
    const int tid = threadIdx.x;
    const int tx = tid & 15;        // n group
    const int ty = tid >> 4;        // m group

    const int lr = tid >> 1;
    const int lk = (tid & 1) * 8;

    const int ma = bm + lr;
    const float* Arow = A + (size_t)(ma >> 5) * a_s0 + (size_t)(ma & 31) * a_s1;
    const float* Wrow = W + (size_t)(bn + lr) * K;

    ull accp[8][4];
#pragma unroll
    for (int i = 0; i < 8; i++)
#pragma unroll
        for (int j = 0; j < 4; j++) accp[i][j] = 0ull;

    for (int k0 = 0; k0 < K; k0 += 16) {
        float4 a0 = *(const float4*)(Arow + k0 + lk);
        float4 a1 = *(const float4*)(Arow + k0 + lk + 4);
        float4 w0 = *(const float4*)(Wrow + k0 + lk);
        float4 w1 = *(const float4*)(Wrow + k0 + lk + 4);

        __syncthreads();
        As[lk + 0][lr] = a0.x; As[lk + 1][lr] = a0.y;
        As[lk + 2][lr] = a0.z; As[lk + 3][lr] = a0.w;
        As[lk + 4][lr] = a1.x; As[lk + 5][lr] = a1.y;
        As[lk + 6][lr] = a1.z; As[lk + 7][lr] = a1.w;
        Ws[lk + 0][lr] = w0.x; Ws[lk + 1][lr] = w0.y;
        Ws[lk + 2][lr] = w0.z; Ws[lk + 3][lr] = w0.w;
        Ws[lk + 4][lr] = w1.x; Ws[lk + 5][lr] = w1.y;
        Ws[lk + 6][lr] = w1.z; Ws[lk + 7][lr] = w1.w;
        __syncthreads();

#pragma unroll
        for (int kk = 0; kk < 16; kk++) {
            float a[8];
            *(float4*)(a)     = *(const float4*)&As[kk][ty * 8];
            *(float4*)(a + 4) = *(const float4*)&As[kk][ty * 8 + 4];
            ulonglong2 wA = *(const ulonglong2*)&Ws[kk][tx * 8];
            ulonglong2 wB = *(const ulonglong2*)&Ws[kk][tx * 8 + 4];
            ull wp0 = wA.x, wp1 = wA.y, wp2 = wB.x, wp3 = wB.y;
#pragma unroll
            for (int i = 0; i < 8; i++) {
                ull ad; DUPF(ad, a[i]);
                FMA2(accp[i][0], ad, wp0);
                FMA2(accp[i][1], ad, wp1);
                FMA2(accp[i][2], ad, wp2);
                FMA2(accp[i][3], ad, wp3);
            }
        }
    }

    const int nbase = bn + tx * 8;
    float bv[8];
    *(float4*)(bv)     = *(const float4*)(bias + nbase);
    *(float4*)(bv + 4) = *(const float4*)(bias + nbase + 4);

#pragma unroll
    for (int i = 0; i < 8; i++) {
        const int m = bm + ty * 8 + i;
        float* crow = C + (size_t)(m >> 5) * c_s0 + (size_t)(m & 31) * c_s1 + nbase;
        float o[8];
#pragma unroll
        for (int j = 0; j < 4; j++) unpk(accp[i][j], o[2 * j], o[2 * j + 1]);
        float4 s0, s1;
        s0.x = o[0] + bv[0]; s0.y = o[1] + bv[1]; s0.z = o[2] + bv[2]; s0.w = o[3] + bv[3];
        s1.x = o[4] + bv[4]; s1.y = o[5] + bv[5]; s1.z = o[6] + bv[6]; s1.w = o[7] + bv[7];
        *(float4*)(crow)     = s0;
        *(float4*)(crow + 4) = s1;
    }
}

// ---------------------------------------------------------------------------
// grid-wide barrier (all NCTA CTAs co-resident)
// ---------------------------------------------------------------------------
__device__ __forceinline__ void grid_barrier()
{
    __syncthreads();
    if (threadIdx.x == 0) {
        unsigned old = *(volatile unsigned*)&g_gen;
        __threadfence();
        if (atomicAdd(&g_count, 1u) == NCTA - 1) {
            g_count = 0;
            __threadfence();
            atomicAdd(&g_gen, 1u);
        } else {
            while (*(volatile unsigned*)&g_gen == old) __nanosleep(64);
        }
        __threadfence();
    }
    __syncthreads();
}

// ---------------------------------------------------------------------------
// Persistent GRU layer scan: 512 steps in one launch.
// grid = 128 CTAs, block = 256. CTA c owns hidden cols [c*8, c*8+8).
// Warp w -> col j = c*8+w (weights for all 3 gates held in registers).
// Lane l -> k-slice [l*32, l*32+32). Butterfly reduction; lane b does the
// gate update for batch b and writes y[s][b][j].
// ---------------------------------------------------------------------------
__global__ __launch_bounds__(256, 1)
void gru_scan(const float* __restrict__ gx,   // [512][32][3072] (bias folded)
              const float* __restrict__ Whh,  // [3072][1024]
              const float* __restrict__ h0,   // [32][1024] zeros
              float* __restrict__ y)          // [512][32][1024]
{
    extern __shared__ float smem[];
    float4*     smh4 = (float4*)smem;                 // 8192 float4 (32 rows x 256 chunks)
    ulonglong2* smh2 = (ulonglong2*)smem;
    float*      gxs  = smem + 8192 * 4;               // [32][28]

    const int tid = threadIdx.x;
    const int w   = tid >> 5;
    const int l   = tid & 31;
    const int lm  = l & 7;
    const int cta = blockIdx.x;
    const int j   = cta * 8 + w;

    // Load this warp-lane's weight slices into registers (held for all 512 steps)
    ull wr[16], wz[16], wn[16];
    {
        const float* br = Whh + (size_t)j * HID + (size_t)l * 32;
        const float* bz = br + (size_t)HID * HID;
        const float* bn_ = bz + (size_t)HID * HID;
#pragma unroll
        for (int i = 0; i < 8; i++) {
            ulonglong2 u = *(const ulonglong2*)(br + i * 4);
            wr[2 * i] = u.x; wr[2 * i + 1] = u.y;
        }
#pragma unroll
        for (int i = 0; i < 8; i++) {
            ulonglong2 u = *(const ulonglong2*)(bz + i * 4);
            wz[2 * i] = u.x; wz[2 * i + 1] = u.y;
        }
#pragma unroll
        for (int i = 0; i < 8; i++) {
            ulonglong2 u = *(const ulonglong2*)(bn_ + i * 4);
            wn[2 * i] = u.x; wn[2 * i + 1] = u.y;
        }
    }

    // precomputed swizzled smem chunk offsets for this lane
    int hoff[8];
#pragma unroll
    for (int i = 0; i < 8; i++) hoff[i] = l * 8 + (i ^ lm);

    const int sw_tid = tid ^ ((tid >> 3) & 7);   // staging swizzle slot

    for (int s = 0; s < SEQ; s++) {
        const float* hin = (s == 0) ? h0 : (y + (size_t)(s - 1) * (BATCH * HID));
        const float* gxsrc = gx + (size_t)s * (BATCH * G3);

        // stage h (32 rows x 256 chunks), swizzled
#pragma unroll 8
        for (int b = 0; b < 32; b++) {
            float4 v = *(const float4*)(hin + (size_t)b * HID + tid * 4);
            smh4[b * 256 + sw_tid] = v;
        }
        // stage this CTA's gx slice: [32 b][3 gates][8 cols]
        if (tid < 192) {
            int bb = tid / 6, rem = tid % 6, g = rem >> 1, half = rem & 1;
            float4 v = *(const float4*)(gxsrc + (size_t)bb * G3 + g * HID + cta * 8 + half * 4);
            *(float4*)(gxs + bb * 28 + g * 8 + half * 4) = v;
        }
        const float hp = hin[(size_t)l * HID + j];   // h_prev[b=l][j]
        __syncthreads();

        float myar = 0.f, myaz = 0.f, myan = 0.f;
#pragma unroll 2
        for (int b = 0; b < 32; b++) {
            ull ar = 0ull, az = 0ull, an = 0ull;
            const ulonglong2* hrow = smh2 + b * 256;
#pragma unroll
            for (int i = 0; i < 8; i++) {
                ulonglong2 h2 = hrow[hoff[i]];
                FMA2(ar, h2.x, wr[2 * i]); FMA2(ar, h2.y, wr[2 * i + 1]);
                FMA2(az, h2.x, wz[2 * i]); FMA2(az, h2.y, wz[2 * i + 1]);
                FMA2(an, h2.x, wn[2 * i]); FMA2(an, h2.y, wn[2 * i + 1]);
            }
            float sr = psum(ar), sz = psum(az), sn = psum(an);
#pragma unroll
            for (int off = 16; off; off >>= 1) {
                sr += __shfl_xor_sync(0xffffffffu, sr, off);
                sz += __shfl_xor_sync(0xffffffffu, sz, off);
                sn += __shfl_xor_sync(0xffffffffu, sn, off);
            }
            if (l == b) { myar = sr; myaz = sz; myan = sn; }
        }

        // gate update for batch b = l, column j
        const float gxr = gxs[l * 28 + w];
        const float gxz = gxs[l * 28 + 8 + w];
        const float gxn = gxs[l * 28 + 16 + w];
        const float r = 1.f / (1.f + __expf(-(gxr + myar)));
        const float z = 1.f / (1.f + __expf(-(gxz + myaz)));
        const float npre = fmaf(r, myan, gxn + myan);
        const float e2 = __expf(2.f * npre);
        const float n = 1.f - 2.f / (e2 + 1.f);
        const float hnew = (1.f - z) * n + z * hp;
        y[(size_t)s * (BATCH * HID) + (size_t)l * HID + j] = hnew;

        __threadfence();
        grid_barrier();
    }
}

// ---------------------------------------------------------------------------
// Tail: new_hidden = stack([h_last0, h_last1])
// ---------------------------------------------------------------------------
__global__ void copy_tail(const float* __restrict__ h0,
                          const float* __restrict__ h1,
                          float* __restrict__ dst)
{
    int i = blockIdx.x * blockDim.x + threadIdx.x;   // 0..32767
    dst[i]               = h0[i];
    dst[BATCH * HID + i] = h1[i];
}

// ---------------------------------------------------------------------------
// kernel_launch
// ---------------------------------------------------------------------------
extern "C" void kernel_launch(void* const* d_in, const int* in_sizes, int n_in,
                              void* d_out, int out_size)
{
    const float* x    = (const float*)d_in[0];
    const float* Wih0 = (const float*)d_in[1];
    const float* Whh0 = (const float*)d_in[2];
    const float* b0   = (const float*)d_in[3];
    const float* Wih1 = (const float*)d_in[4];
    const float* Whh1 = (const float*)d_in[5];
    const float* b1   = (const float*)d_in[6];
    const float* Wlin = (const float*)d_in[7];
    const float* blin = (const float*)d_in[8];
    float* out = (float*)d_out;

    float *gx, *y0, *y1, *h0;
    cudaGetSymbolAddress((void**)&gx, g_gx);
    cudaGetSymbolAddress((void**)&y0, g_y0);
    cudaGetSymbolAddress((void**)&y1, g_y1);
    cudaGetSymbolAddress((void**)&h0, g_h0);

    const int SCAN_SMEM = 8192 * 16 + 32 * 28 * 4;   // 134656 bytes
    cudaFuncSetAttribute(gru_scan, cudaFuncAttributeMaxDynamicSharedMemorySize, SCAN_SMEM);

    // 1) GX = x @ Wih0^T + b0, time-major [t][b][:]
    sgemm_nt<<<dim3(G3 / 128, (SEQ * BATCH) / 128), 256>>>(
        x, Wih0, b0, gx, IN_D,
        /*a_s0=*/IN_D, /*a_s1=*/SEQ * IN_D,
        /*c_s0=*/BATCH * G3, /*c_s1=*/G3);

    // 2) layer-0 scan (persistent)
    gru_scan<<<NCTA, 256, SCAN_SMEM>>>(gx, Whh0, h0, y0);

    // 3) GX = Y0 @ Wih1^T + b1
    sgemm_nt<<<dim3(G3 / 128, (SEQ * BATCH) / 128), 256>>>(
        y0, Wih1, b1, gx, HID,
        /*a_s0=*/BATCH * HID, /*a_s1=*/HID,
        /*c_s0=*/BATCH * G3, /*c_s1=*/G3);

    // 4) layer-1 scan (persistent)
    gru_scan<<<NCTA, 256, SCAN_SMEM>>>(gx, Whh1, h0, y1);

    // 5) out[b][t][:] = Y1[t][b][:] @ Wlin^T + blin
    sgemm_nt<<<dim3(IN_D / 128, (SEQ * BATCH) / 128), 256>>>(
        y1, Wlin, blin, out, HID,
        /*a_s0=*/BATCH * HID, /*a_s1=*/HID,
        /*c_s0=*/IN_D, /*c_s1=*/SEQ * IN_D);

    // 6) new_hidden tail
    copy_tail<<<128, 256>>>(y0 + (size_t)(SEQ - 1) * BATCH * HID,
                            y1 + (size_t)(SEQ - 1) * BATCH * HID,
                            out + (size_t)BATCH * SEQ * IN_D);
}